// round 5
// baseline (speedup 1.0000x reference)
#include <cuda_runtime.h>
#include <cstdint>

#define BB 32
#define PP 4096
#define QQ 64
#define DD 128
#define NT 8
#define TILE 512
#define NEGBIG (-1e30f)
#define POSBIG (1e30f)

// ---- main kernel smem layout (floats) ----
#define SM_U     0                    // U_s  [q*132 + d]      64*132 = 8448
#define SM_VT    8448                 // Vt_s [d*68 + q]       128*68 = 8704
#define SM_W     17152                // w_s  per warp 16*68   8*1088 = 8704
#define SM_HC    25856                // H stage / c2q alias   8*16*132 = 16896
#define SM_MZ    42752                // rowmz per warp 16*2   8*32 = 256
#define SM_TOK   43008                // tok (int)             512
#define SM_RED   43520                // reduction             8*128 = 1024
#define SM_MZS   44544                // warp M/Z              16
#define SM_TOTAL 44560
#define SMEM_BYTES (SM_TOTAL * 4)

#define VT_SMEM_BYTES ((64 * 129 + 32 * 128) * 4)

// scratch
__device__ float g_Vt[BB * DD * QQ];         // Vt[b][d][q]
__device__ float g_part[BB * NT * 1024];     // per (b,tile) partials

// ---------------------------------------------------------------------------
__device__ __forceinline__ void mma_tf32(float* d,
    uint32_t a0, uint32_t a1, uint32_t a2, uint32_t a3,
    uint32_t b0, uint32_t b1)
{
    asm volatile(
        "mma.sync.aligned.m16n8k8.row.col.f32.tf32.tf32.f32 "
        "{%0,%1,%2,%3}, {%4,%5,%6,%7}, {%8,%9}, {%0,%1,%2,%3};"
        : "+f"(d[0]), "+f"(d[1]), "+f"(d[2]), "+f"(d[3])
        : "r"(a0), "r"(a1), "r"(a2), "r"(a3), "r"(b0), "r"(b1));
}

__device__ __forceinline__ void split2(float x, uint32_t& hi, uint32_t& lo) {
    uint32_t xb = __float_as_uint(x);
    hi = xb & 0xFFFFE000u;                         // tf32 truncation (exact)
    lo = __float_as_uint(x - __uint_as_float(hi)); // exact residual
}

// ---------------------------------------------------------------------------
// Kernel 1: Vt[b][d][q] = sum_e W[d,e]*U[b,q,e]. grid (4, 32), 256 threads.
// ---------------------------------------------------------------------------
__global__ void vt_kernel(const float* __restrict__ U, const float* __restrict__ W) {
    extern __shared__ float vsm[];
    float* U_s = vsm;             // 64*129
    float* W_s = vsm + 64 * 129;  // 32*128
    int b = blockIdx.y, dbase = blockIdx.x * 32, tid = threadIdx.x;

    const float* Ub = U + (size_t)b * QQ * DD;
    for (int i = tid; i < QQ * DD; i += 256)
        U_s[(i >> 7) * 129 + (i & 127)] = Ub[i];
    for (int i = tid; i < 32 * DD; i += 256)
        W_s[i] = W[(size_t)dbase * DD + i];
    __syncthreads();

    int q = tid & 63, dg = tid >> 6;    // dg warp-uniform -> W_s broadcast
    float acc[8];
#pragma unroll
    for (int k = 0; k < 8; k++) acc[k] = 0.f;
#pragma unroll 4
    for (int e = 0; e < DD; e++) {
        float u = U_s[q * 129 + e];
#pragma unroll
        for (int k = 0; k < 8; k++)
            acc[k] += u * W_s[(dg * 8 + k) * DD + e];
    }
#pragma unroll
    for (int k = 0; k < 8; k++)
        g_Vt[((size_t)b * DD + dbase + dg * 8 + k) * QQ + q] = acc[k];
}

// ---------------------------------------------------------------------------
// Kernel 2: fused attention via 3xTF32 mma + pooling partials.
// grid (NT, 32), 256 threads (8 warps), 1 CTA/SM. Warp: 16 p-rows/group, 4 groups.
// ---------------------------------------------------------------------------
__global__ void __launch_bounds__(256, 1) main_kernel(
    const float* __restrict__ H, const float* __restrict__ U,
    const float* __restrict__ Mm, const int* __restrict__ tok)
{
    extern __shared__ float sm[];
    float* U_s   = sm + SM_U;
    float* Vt_s  = sm + SM_VT;
    float* w_sb  = sm + SM_W;
    float* hc_sb = sm + SM_HC;
    float* mz_sb = sm + SM_MZ;
    int*   tok_s = (int*)(sm + SM_TOK);
    float* red   = sm + SM_RED;
    float* mzs   = sm + SM_MZS;

    int t = blockIdx.x, b = blockIdx.y;
    int pstart = t * TILE;
    int tid = threadIdx.x, wid = tid >> 5, lane = tid & 31;
    int g = lane >> 2, tg = lane & 3;

    // ---- stage U, Vt, tok ----
    const float* Ub = U + (size_t)b * QQ * DD;
    for (int i = tid; i < 2048; i += 256) {
        int q = i >> 5, dc = i & 31;
        *(float4*)(U_s + q * 132 + dc * 4) = ((const float4*)Ub)[i];
    }
    const float* Vtb = g_Vt + (size_t)b * DD * QQ;
    for (int i = tid; i < 2048; i += 256) {
        int d = i >> 4, qc = i & 15;
        *(float4*)(Vt_s + d * 68 + qc * 4) = ((const float4*)Vtb)[i];
    }
    const int* tokb = tok + (size_t)b * PP + pstart;
    for (int i = tid; i < TILE; i += 256) tok_s[i] = tokb[i];
    __syncthreads();

    float* myw  = w_sb + wid * 16 * 68;
    float* myhc = hc_sb + wid * 16 * 132;
    float* mymz = mz_sb + wid * 32;

    // per-warp running partials (lane covers d = 4*lane + j)
    float pm_h[4], pm_c[4], pm_hc[4], pm_m[4], mxh[4], mnh[4], qacc[4];
#pragma unroll
    for (int j = 0; j < 4; j++) {
        pm_h[j] = NEGBIG; pm_c[j] = NEGBIG; pm_hc[j] = NEGBIG; pm_m[j] = NEGBIG;
        mxh[j] = NEGBIG;  mnh[j] = POSBIG;  qacc[j] = 0.f;
    }
    float Mw = NEGBIG, Zw = 0.f;

    for (int it = 0; it < 4; it++) {
        int p0 = pstart + it * 128 + wid * 16;
        const float* Hp = H + ((size_t)b * PP + p0) * DD;
        const float* Mp = Mm + ((size_t)b * PP + p0) * DD;

        // ---- stage 16 H rows ----
#pragma unroll
        for (int i = 0; i < 16; i++)
            *(float4*)(myhc + i * 132 + 4 * lane) = *(const float4*)(Hp + i * DD + 4 * lane);
        __syncwarp();

        // ---- S = H . Vt^T via 3xTF32; accum C layout m16n8, 8 ntiles ----
        float sacc[8][4];
#pragma unroll
        for (int nt = 0; nt < 8; nt++)
            sacc[nt][0] = sacc[nt][1] = sacc[nt][2] = sacc[nt][3] = 0.f;

#pragma unroll 2
        for (int kt = 0; kt < 16; kt++) {
            uint32_t ahi[4], alo[4];
            split2(myhc[g * 132 + 8 * kt + tg],           ahi[0], alo[0]);
            split2(myhc[(g + 8) * 132 + 8 * kt + tg],     ahi[1], alo[1]);
            split2(myhc[g * 132 + 8 * kt + tg + 4],       ahi[2], alo[2]);
            split2(myhc[(g + 8) * 132 + 8 * kt + tg + 4], ahi[3], alo[3]);
#pragma unroll
            for (int nt = 0; nt < 8; nt++) {
                uint32_t bhi0, blo0, bhi1, blo1;
                split2(Vt_s[(8 * kt + tg) * 68 + 8 * nt + g],     bhi0, blo0);
                split2(Vt_s[(8 * kt + tg + 4) * 68 + 8 * nt + g], bhi1, blo1);
                mma_tf32(sacc[nt], ahi[0], ahi[1], ahi[2], ahi[3], bhi0, bhi1);
                mma_tf32(sacc[nt], ahi[0], ahi[1], ahi[2], ahi[3], blo0, blo1);
                mma_tf32(sacc[nt], alo[0], alo[1], alo[2], alo[3], bhi0, bhi1);
            }
        }

        // ---- softmax over q: rows (g) and (g+8) ----
        float m0 = NEGBIG, m1 = NEGBIG;
#pragma unroll
        for (int nt = 0; nt < 8; nt++) {
            m0 = fmaxf(m0, fmaxf(sacc[nt][0], sacc[nt][1]));
            m1 = fmaxf(m1, fmaxf(sacc[nt][2], sacc[nt][3]));
        }
        m0 = fmaxf(m0, __shfl_xor_sync(0xffffffffu, m0, 1));
        m0 = fmaxf(m0, __shfl_xor_sync(0xffffffffu, m0, 2));
        m1 = fmaxf(m1, __shfl_xor_sync(0xffffffffu, m1, 1));
        m1 = fmaxf(m1, __shfl_xor_sync(0xffffffffu, m1, 2));

        float z0 = 0.f, z1 = 0.f;
#pragma unroll
        for (int nt = 0; nt < 8; nt++) {
            sacc[nt][0] = __expf(sacc[nt][0] - m0);
            sacc[nt][1] = __expf(sacc[nt][1] - m0);
            sacc[nt][2] = __expf(sacc[nt][2] - m1);
            sacc[nt][3] = __expf(sacc[nt][3] - m1);
            z0 += sacc[nt][0] + sacc[nt][1];
            z1 += sacc[nt][2] + sacc[nt][3];
        }
        z0 += __shfl_xor_sync(0xffffffffu, z0, 1);
        z0 += __shfl_xor_sync(0xffffffffu, z0, 2);
        z1 += __shfl_xor_sync(0xffffffffu, z1, 1);
        z1 += __shfl_xor_sync(0xffffffffu, z1, 2);

        // store unnormalized e to w_s; stash (m,z) per row
#pragma unroll
        for (int nt = 0; nt < 8; nt++) {
            *(float2*)(myw + g * 68 + 8 * nt + 2 * tg)       = make_float2(sacc[nt][0], sacc[nt][1]);
            *(float2*)(myw + (g + 8) * 68 + 8 * nt + 2 * tg) = make_float2(sacc[nt][2], sacc[nt][3]);
        }
        if (tg == 0) {
            mymz[2 * g] = m0;            mymz[2 * g + 1] = z0;
            mymz[2 * (g + 8)] = m1;      mymz[2 * (g + 8) + 1] = z1;
        }
        __syncwarp();

        // ---- c2q_raw = e . U via 3xTF32; 16 ntiles over d ----
        float cacc[16][4];
#pragma unroll
        for (int nt = 0; nt < 16; nt++)
            cacc[nt][0] = cacc[nt][1] = cacc[nt][2] = cacc[nt][3] = 0.f;

#pragma unroll 2
        for (int kt = 0; kt < 8; kt++) {
            uint32_t ahi[4], alo[4];
            split2(myw[g * 68 + 8 * kt + tg],           ahi[0], alo[0]);
            split2(myw[(g + 8) * 68 + 8 * kt + tg],     ahi[1], alo[1]);
            split2(myw[g * 68 + 8 * kt + tg + 4],       ahi[2], alo[2]);
            split2(myw[(g + 8) * 68 + 8 * kt + tg + 4], ahi[3], alo[3]);
#pragma unroll
            for (int nt = 0; nt < 16; nt++) {
                uint32_t bhi0, blo0, bhi1, blo1;
                split2(U_s[(8 * kt + tg) * 132 + 8 * nt + g],     bhi0, blo0);
                split2(U_s[(8 * kt + tg + 4) * 132 + 8 * nt + g], bhi1, blo1);
                mma_tf32(cacc[nt], ahi[0], ahi[1], ahi[2], ahi[3], bhi0, bhi1);
                mma_tf32(cacc[nt], ahi[0], ahi[1], ahi[2], ahi[3], blo0, blo1);
                mma_tf32(cacc[nt], alo[0], alo[1], alo[2], alo[3], bhi0, bhi1);
            }
        }
        __syncwarp();   // H-frag reads done; safe to overwrite myhc with c2q

#pragma unroll
        for (int nt = 0; nt < 16; nt++) {
            *(float2*)(myhc + g * 132 + 8 * nt + 2 * tg)       = make_float2(cacc[nt][0], cacc[nt][1]);
            *(float2*)(myhc + (g + 8) * 132 + 8 * nt + 2 * tg) = make_float2(cacc[nt][2], cacc[nt][3]);
        }
        __syncwarp();

        // ---- elementwise pooling pass (lane owns d = 4*lane..+3) ----
#pragma unroll 2
        for (int i = 0; i < 16; i++) {
            float m = mymz[2 * i], z = mymz[2 * i + 1];
            float invz = 1.0f / z;
            float4 c4 = *(float4*)(myhc + i * 132 + 4 * lane);
            float cv[4] = {c4.x * invz, c4.y * invz, c4.z * invz, c4.w * invz};
            float4 h4 = *(const float4*)(Hp + i * DD + 4 * lane);   // L2-hot re-read
            float hv[4] = {h4.x, h4.y, h4.z, h4.w};

            // online q2c stats (unmasked)
            float nM = fmaxf(Mw, m);
            float aa = __expf(Mw - nM);
            float ee = __expf(m - nM);
#pragma unroll
            for (int j = 0; j < 4; j++) qacc[j] = qacc[j] * aa + ee * hv[j];
            Zw = Zw * aa + ee;
            Mw = nM;

            int tk = tok_s[it * 128 + wid * 16 + i];
            if (tk != 0) {
                float4 m4 = *(const float4*)(Mp + i * DD + 4 * lane);
                float mv[4] = {m4.x, m4.y, m4.z, m4.w};
#pragma unroll
                for (int j = 0; j < 4; j++) {
                    pm_h[j]  = fmaxf(pm_h[j],  hv[j]);
                    pm_c[j]  = fmaxf(pm_c[j],  cv[j]);
                    pm_hc[j] = fmaxf(pm_hc[j], hv[j] * cv[j]);
                    pm_m[j]  = fmaxf(pm_m[j],  mv[j]);
                    mxh[j]   = fmaxf(mxh[j],   hv[j]);
                    mnh[j]   = fminf(mnh[j],   hv[j]);
                }
            }
        }
        __syncwarp();
    }

    // ---------------- block reduction -> tile partials ----------------
    __syncthreads();
    if (lane == 0) { mzs[wid * 2] = Mw; mzs[wid * 2 + 1] = Zw; }
    __syncthreads();
    float Mb = mzs[0];
#pragma unroll
    for (int w = 1; w < 8; w++) Mb = fmaxf(Mb, mzs[2 * w]);

    float* pout = g_part + ((size_t)b * NT + t) * 1024;
    float sc = __expf(Mw - Mb);   // Mw lane-uniform

    *(float4*)(red + wid * DD + 4 * lane) =
        make_float4(qacc[0] * sc, qacc[1] * sc, qacc[2] * sc, qacc[3] * sc);
    __syncthreads();
    if (tid < DD) {
        float r = 0.f;
#pragma unroll
        for (int w = 0; w < 8; w++) r += red[w * DD + tid];
        pout[tid] = r;
    }

#define BLK_MAXRED(arr, off)                                                   \
    do {                                                                       \
        __syncthreads();                                                       \
        *(float4*)(red + wid * DD + 4 * lane) =                                \
            make_float4((arr)[0], (arr)[1], (arr)[2], (arr)[3]);               \
        __syncthreads();                                                       \
        if (tid < DD) {                                                        \
            float r = red[tid];                                                \
            for (int w = 1; w < 8; w++) r = fmaxf(r, red[w * DD + tid]);       \
            pout[(off) + tid] = r;                                             \
        }                                                                      \
    } while (0)

    BLK_MAXRED(pm_h, 128);
    BLK_MAXRED(pm_c, 256);
    BLK_MAXRED(pm_hc, 384);
    BLK_MAXRED(pm_m, 512);
    BLK_MAXRED(mxh, 640);

    __syncthreads();
    *(float4*)(red + wid * DD + 4 * lane) = make_float4(mnh[0], mnh[1], mnh[2], mnh[3]);
    __syncthreads();
    if (tid < DD) {
        float r = red[tid];
#pragma unroll
        for (int w = 1; w < 8; w++) r = fminf(r, red[w * DD + tid]);
        pout[768 + tid] = r;
    }

    if (tid == 0) {
        float Zt = 0.f;
#pragma unroll
        for (int w = 0; w < 8; w++) Zt += mzs[2 * w + 1] * __expf(mzs[2 * w] - Mb);
        pout[896] = Mb;
        pout[897] = Zt;
    }
}

// ---------------------------------------------------------------------------
// Kernel 3: per-batch tile combine + classifier. grid 32, 128 threads.
// ---------------------------------------------------------------------------
__global__ void finalize_kernel(const float* __restrict__ Wcls, float* __restrict__ out) {
    int b = blockIdx.x, d = threadIdx.x;
    const float* base = g_part + (size_t)b * NT * 1024;

    float Mg = NEGBIG;
#pragma unroll
    for (int t = 0; t < NT; t++) Mg = fmaxf(Mg, base[t * 1024 + 896]);

    float Z = 0.f, qa = 0.f;
    float ph = NEGBIG, pc = NEGBIG, phc = NEGBIG, pm = NEGBIG, xh = NEGBIG, nh = POSBIG;
#pragma unroll
    for (int t = 0; t < NT; t++) {
        const float* pt = base + t * 1024;
        float scv = __expf(pt[896] - Mg);
        Z  += pt[897] * scv;
        qa += pt[d] * scv;
        ph  = fmaxf(ph,  pt[128 + d]);
        pc  = fmaxf(pc,  pt[256 + d]);
        phc = fmaxf(phc, pt[384 + d]);
        pm  = fmaxf(pm,  pt[512 + d]);
        xh  = fmaxf(xh,  pt[640 + d]);
        nh  = fminf(nh,  pt[768 + d]);
    }
    float q2c = qa / Z;
    float phq = fmaxf(q2c * xh, q2c * nh);

    float o0 = ph  * Wcls[2 * d]
             + pc  * Wcls[2 * (128 + d)]
             + phc * Wcls[2 * (256 + d)]
             + phq * Wcls[2 * (384 + d)]
             + pm  * Wcls[2 * (512 + d)];
    float o1 = ph  * Wcls[2 * d + 1]
             + pc  * Wcls[2 * (128 + d) + 1]
             + phc * Wcls[2 * (256 + d) + 1]
             + phq * Wcls[2 * (384 + d) + 1]
             + pm  * Wcls[2 * (512 + d) + 1];

    __shared__ float r0[128], r1[128];
    r0[d] = o0; r1[d] = o1;
    __syncthreads();
    for (int s = 64; s > 0; s >>= 1) {
        if (d < s) { r0[d] += r0[d + s]; r1[d] += r1[d + s]; }
        __syncthreads();
    }
    if (d == 0) { out[b * 2] = r0[0]; out[b * 2 + 1] = r1[0]; }
}

// ---------------------------------------------------------------------------
extern "C" void kernel_launch(void* const* d_in, const int* in_sizes, int n_in,
                              void* d_out, int out_size) {
    const float* H     = (const float*)d_in[0];
    const float* U     = (const float*)d_in[1];
    const float* Mm    = (const float*)d_in[2];
    const int*   tok   = (const int*)d_in[3];    // int32 on the wire
    const float* Wattn = (const float*)d_in[4];
    const float* Wcls  = (const float*)d_in[5];
    float*       out   = (float*)d_out;

    cudaFuncSetAttribute(vt_kernel, cudaFuncAttributeMaxDynamicSharedMemorySize, VT_SMEM_BYTES);
    cudaFuncSetAttribute(main_kernel, cudaFuncAttributeMaxDynamicSharedMemorySize, SMEM_BYTES);

    vt_kernel<<<dim3(4, BB), 256, VT_SMEM_BYTES>>>(U, Wattn);
    main_kernel<<<dim3(NT, BB), 256, SMEM_BYTES>>>(H, U, Mm, tok);
    finalize_kernel<<<BB, 128>>>(Wcls, out);
}

// round 7
// speedup vs baseline: 1.1743x; 1.1743x over previous
#include <cuda_runtime.h>
#include <cuda_bf16.h>
#include <cstdint>

#define BB 32
#define PP 4096
#define QQ 64
#define DD 128
#define NT 8
#define TILE 512
#define NEGBIG (-1e30f)
#define POSBIG (1e30f)

// ---- main kernel smem layout (32-bit words) ----
#define SM_UHI   0        // U hi packed  [pq*136 + d]   32*136 = 4352
#define SM_ULO   4352     // U lo packed                  4352
#define SM_VTHI  8704     // Vt hi packed [pd*72 + q]    64*72  = 4608
#define SM_VTLO  13312    // Vt lo packed                 4608
#define SM_WHI   17920    // e hi packed, per warp 16*36  8*576 = 4608
#define SM_WLO   22528    // e lo packed                  4608
#define SM_HC    27136    // per warp: packed H (2*1088) / later c2q fp32 (2112); 8*2176 = 17408
#define SM_MZ    44544    // per warp row (m,z) 16*2      8*32 = 256
#define SM_TOK   44800    // tok ints                     512
#define SM_RED   45312    // block reduction              1024
#define SM_MZS   46336    // warp M/Z                     16
#define SM_TOTAL 46352
#define SMEM_BYTES (SM_TOTAL * 4)

// device scratch (zero-initialized)
__device__ float g_Vt[BB * DD * QQ];      // Vt[b][d][q]
__device__ float g_part[BB * NT * 1024];  // per (b,tile) partials
__device__ int   g_cnt[BB];               // arrival counters (left 0 after each call)

// ---------------------------------------------------------------------------
__device__ __forceinline__ void mma_bf16(float* d,
    uint32_t a0, uint32_t a1, uint32_t a2, uint32_t a3,
    uint32_t b0, uint32_t b1)
{
    asm volatile(
        "mma.sync.aligned.m16n8k16.row.col.f32.bf16.bf16.f32 "
        "{%0,%1,%2,%3}, {%4,%5,%6,%7}, {%8,%9}, {%0,%1,%2,%3};"
        : "+f"(d[0]), "+f"(d[1]), "+f"(d[2]), "+f"(d[3])
        : "r"(a0), "r"(a1), "r"(a2), "r"(a3), "r"(b0), "r"(b1));
}

// split (x0,x1) into packed bf16x2 hi and lo (x = hi + lo + O(2^-17 x))
__device__ __forceinline__ void packsplit(float x0, float x1, uint32_t& hi, uint32_t& lo) {
    __nv_bfloat162 h = __float22bfloat162_rn(make_float2(x0, x1));
    float2 hf = __bfloat1622float2(h);
    __nv_bfloat162 l = __float22bfloat162_rn(make_float2(x0 - hf.x, x1 - hf.y));
    hi = *reinterpret_cast<uint32_t*>(&h);
    lo = *reinterpret_cast<uint32_t*>(&l);
}

// ---------------------------------------------------------------------------
// Kernel 1: Vt[b][d][q] = sum_e W[d,e]*U[b,q,e] (fp32 exact). grid (8,32).
// ---------------------------------------------------------------------------
__global__ void vt_kernel(const float* __restrict__ U, const float* __restrict__ W) {
    __shared__ float U_s[QQ * 129];
    __shared__ float W_s[16 * DD];
    int b = blockIdx.y, dbase = blockIdx.x * 16, tid = threadIdx.x;

    const float* Ub = U + (size_t)b * QQ * DD;
    for (int i = tid; i < QQ * DD; i += 256)
        U_s[(i >> 7) * 129 + (i & 127)] = Ub[i];
    for (int i = tid; i < 16 * DD; i += 256)
        W_s[i] = W[(size_t)dbase * DD + i];
    __syncthreads();

    int q = tid & 63, dg = tid >> 6;
    float acc[4] = {0.f, 0.f, 0.f, 0.f};
#pragma unroll 4
    for (int e = 0; e < DD; e++) {
        float u = U_s[q * 129 + e];
#pragma unroll
        for (int k = 0; k < 4; k++)
            acc[k] += u * W_s[(dg * 4 + k) * DD + e];
    }
#pragma unroll
    for (int k = 0; k < 4; k++)
        g_Vt[((size_t)b * DD + dbase + dg * 4 + k) * QQ + q] = acc[k];
}

// ---------------------------------------------------------------------------
// Kernel 2: fused attention (bf16-split MMA) + pooling + fused finalize.
// grid (NT, 32), 256 threads, 1 CTA/SM. Warp owns 16 p-rows per iteration.
// ---------------------------------------------------------------------------
__global__ void __launch_bounds__(256, 1) main_kernel(
    const float* __restrict__ H, const float* __restrict__ U,
    const float* __restrict__ Mm, const int* __restrict__ tok,
    const float* __restrict__ Wcls, float* __restrict__ out)
{
    extern __shared__ float sm[];
    uint32_t* U_hi  = (uint32_t*)(sm + SM_UHI);
    uint32_t* U_lo  = (uint32_t*)(sm + SM_ULO);
    uint32_t* Vt_hi = (uint32_t*)(sm + SM_VTHI);
    uint32_t* Vt_lo = (uint32_t*)(sm + SM_VTLO);
    uint32_t* w_hi  = (uint32_t*)(sm + SM_WHI);
    uint32_t* w_lo  = (uint32_t*)(sm + SM_WLO);
    float*    hc_sb = sm + SM_HC;
    float*    mz_sb = sm + SM_MZ;
    int*      tok_s = (int*)(sm + SM_TOK);
    float*    red   = sm + SM_RED;
    float*    mzs   = sm + SM_MZS;
    __shared__ int s_last;

    int t = blockIdx.x, b = blockIdx.y;
    int pstart = t * TILE;
    int tid = threadIdx.x, wid = tid >> 5, lane = tid & 31;
    int g = lane >> 2, tg = lane & 3;

    // ---- stage packed U (pairs over q), packed Vt (pairs over d), tok ----
    const float* Ub = U + (size_t)b * QQ * DD;
    for (int i = tid; i < 32 * DD; i += 256) {
        int pq = i >> 7, d = i & 127;
        uint32_t hi, lo;
        packsplit(Ub[(2 * pq) * DD + d], Ub[(2 * pq + 1) * DD + d], hi, lo);
        U_hi[pq * 136 + d] = hi; U_lo[pq * 136 + d] = lo;
    }
    const float* Vtb = g_Vt + (size_t)b * DD * QQ;
    for (int i = tid; i < 64 * QQ; i += 256) {
        int pd = i >> 6, q = i & 63;
        uint32_t hi, lo;
        packsplit(Vtb[(2 * pd) * QQ + q], Vtb[(2 * pd + 1) * QQ + q], hi, lo);
        Vt_hi[pd * 72 + q] = hi; Vt_lo[pd * 72 + q] = lo;
    }
    const int* tokb = tok + (size_t)b * PP + pstart;
    for (int i = tid; i < TILE; i += 256) tok_s[i] = tokb[i];
    __syncthreads();

    uint32_t* myh_hi = (uint32_t*)(hc_sb + wid * 2176);
    uint32_t* myh_lo = myh_hi + 1088;
    float*    myhc   = hc_sb + wid * 2176;     // c2q fp32 output aliases H stage
    uint32_t* myw_hi = w_hi + wid * 576;
    uint32_t* myw_lo = w_lo + wid * 576;
    float*    mymz   = mz_sb + wid * 32;

    // per-warp running partials (lane covers d = 4*lane + j)
    float pm_h[4], pm_c[4], pm_hc[4], pm_m[4], mxh[4], mnh[4], qacc[4];
#pragma unroll
    for (int j = 0; j < 4; j++) {
        pm_h[j] = NEGBIG; pm_c[j] = NEGBIG; pm_hc[j] = NEGBIG; pm_m[j] = NEGBIG;
        mxh[j] = NEGBIG;  mnh[j] = POSBIG;  qacc[j] = 0.f;
    }
    float Mw = NEGBIG, Zw = 0.f;

    for (int it = 0; it < 4; it++) {
        int p0 = pstart + it * 128 + wid * 16;
        const float* Hp = H + ((size_t)b * PP + p0) * DD;
        const float* Mp = Mm + ((size_t)b * PP + p0) * DD;

        // ---- stage 16 H rows as packed bf16 hi/lo (pairs over d) ----
#pragma unroll
        for (int i = 0; i < 16; i++) {
            float4 h = *(const float4*)(Hp + i * DD + 4 * lane);
            uint32_t h01, l01, h23, l23;
            packsplit(h.x, h.y, h01, l01);
            packsplit(h.z, h.w, h23, l23);
            *(uint2*)(myh_hi + i * 68 + 2 * lane) = make_uint2(h01, h23);
            *(uint2*)(myh_lo + i * 68 + 2 * lane) = make_uint2(l01, l23);
        }
        __syncwarp();

        // ---- S = H . Vt^T  (3-term bf16 split, m16n8k16) ----
        float sacc[8][4];
#pragma unroll
        for (int nt = 0; nt < 8; nt++)
            sacc[nt][0] = sacc[nt][1] = sacc[nt][2] = sacc[nt][3] = 0.f;

#pragma unroll
        for (int kt = 0; kt < 8; kt++) {
            int ra = g * 68 + 8 * kt + tg, rb = (g + 8) * 68 + 8 * kt + tg;
            uint32_t ah0 = myh_hi[ra], ah1 = myh_hi[rb], ah2 = myh_hi[ra + 4], ah3 = myh_hi[rb + 4];
            uint32_t al0 = myh_lo[ra], al1 = myh_lo[rb], al2 = myh_lo[ra + 4], al3 = myh_lo[rb + 4];
            uint32_t bh[8][2], bl[8][2];
#pragma unroll
            for (int nt = 0; nt < 8; nt++) {
                int c = 8 * nt + g;
                bh[nt][0] = Vt_hi[(8 * kt + tg) * 72 + c];
                bh[nt][1] = Vt_hi[(8 * kt + tg + 4) * 72 + c];
                bl[nt][0] = Vt_lo[(8 * kt + tg) * 72 + c];
                bl[nt][1] = Vt_lo[(8 * kt + tg + 4) * 72 + c];
            }
#pragma unroll
            for (int nt = 0; nt < 8; nt++)
                mma_bf16(sacc[nt], ah0, ah1, ah2, ah3, bh[nt][0], bh[nt][1]);
#pragma unroll
            for (int nt = 0; nt < 8; nt++)
                mma_bf16(sacc[nt], ah0, ah1, ah2, ah3, bl[nt][0], bl[nt][1]);
#pragma unroll
            for (int nt = 0; nt < 8; nt++)
                mma_bf16(sacc[nt], al0, al1, al2, al3, bh[nt][0], bh[nt][1]);
        }

        // ---- softmax over q: rows g and g+8 ----
        float m0 = NEGBIG, m1 = NEGBIG;
#pragma unroll
        for (int nt = 0; nt < 8; nt++) {
            m0 = fmaxf(m0, fmaxf(sacc[nt][0], sacc[nt][1]));
            m1 = fmaxf(m1, fmaxf(sacc[nt][2], sacc[nt][3]));
        }
        m0 = fmaxf(m0, __shfl_xor_sync(0xffffffffu, m0, 1));
        m0 = fmaxf(m0, __shfl_xor_sync(0xffffffffu, m0, 2));
        m1 = fmaxf(m1, __shfl_xor_sync(0xffffffffu, m1, 1));
        m1 = fmaxf(m1, __shfl_xor_sync(0xffffffffu, m1, 2));

        float z0 = 0.f, z1 = 0.f;
#pragma unroll
        for (int nt = 0; nt < 8; nt++) {
            sacc[nt][0] = __expf(sacc[nt][0] - m0);
            sacc[nt][1] = __expf(sacc[nt][1] - m0);
            sacc[nt][2] = __expf(sacc[nt][2] - m1);
            sacc[nt][3] = __expf(sacc[nt][3] - m1);
            z0 += sacc[nt][0] + sacc[nt][1];
            z1 += sacc[nt][2] + sacc[nt][3];
        }
        z0 += __shfl_xor_sync(0xffffffffu, z0, 1);
        z0 += __shfl_xor_sync(0xffffffffu, z0, 2);
        z1 += __shfl_xor_sync(0xffffffffu, z1, 1);
        z1 += __shfl_xor_sync(0xffffffffu, z1, 2);

        // ---- store unnormalized e as packed bf16 hi/lo (pairs over q) ----
#pragma unroll
        for (int nt = 0; nt < 8; nt++) {
            uint32_t hi, lo;
            packsplit(sacc[nt][0], sacc[nt][1], hi, lo);
            myw_hi[g * 36 + 4 * nt + tg] = hi; myw_lo[g * 36 + 4 * nt + tg] = lo;
            packsplit(sacc[nt][2], sacc[nt][3], hi, lo);
            myw_hi[(g + 8) * 36 + 4 * nt + tg] = hi; myw_lo[(g + 8) * 36 + 4 * nt + tg] = lo;
        }
        if (tg == 0) {
            mymz[2 * g] = m0;           mymz[2 * g + 1] = z0;
            mymz[2 * (g + 8)] = m1;     mymz[2 * (g + 8) + 1] = z1;
        }
        __syncwarp();

        // ---- c2q_raw = e . U  (3-term bf16 split) ----
        float cacc[16][4];
#pragma unroll
        for (int nt = 0; nt < 16; nt++)
            cacc[nt][0] = cacc[nt][1] = cacc[nt][2] = cacc[nt][3] = 0.f;

#pragma unroll
        for (int kt = 0; kt < 4; kt++) {
            int ra = g * 36 + 8 * kt + tg, rb = (g + 8) * 36 + 8 * kt + tg;
            uint32_t ah0 = myw_hi[ra], ah1 = myw_hi[rb], ah2 = myw_hi[ra + 4], ah3 = myw_hi[rb + 4];
            uint32_t al0 = myw_lo[ra], al1 = myw_lo[rb], al2 = myw_lo[ra + 4], al3 = myw_lo[rb + 4];
#pragma unroll
            for (int nt = 0; nt < 16; nt++) {
                int c = 8 * nt + g;
                int r0i = (8 * kt + tg) * 136 + c, r1i = (8 * kt + tg + 4) * 136 + c;
                uint32_t bh0 = U_hi[r0i], bh1 = U_hi[r1i];
                uint32_t bl0 = U_lo[r0i], bl1 = U_lo[r1i];
                mma_bf16(cacc[nt], ah0, ah1, ah2, ah3, bh0, bh1);
                mma_bf16(cacc[nt], ah0, ah1, ah2, ah3, bl0, bl1);
                mma_bf16(cacc[nt], al0, al1, al2, al3, bh0, bh1);
            }
        }
        __syncwarp();   // packed H no longer needed; overwrite region with c2q fp32

#pragma unroll
        for (int nt = 0; nt < 16; nt++) {
            *(float2*)(myhc + g * 132 + 8 * nt + 2 * tg)       = make_float2(cacc[nt][0], cacc[nt][1]);
            *(float2*)(myhc + (g + 8) * 132 + 8 * nt + 2 * tg) = make_float2(cacc[nt][2], cacc[nt][3]);
        }
        __syncwarp();

        // ---- elementwise pooling (lane owns d = 4*lane..+3) ----
#pragma unroll 2
        for (int i = 0; i < 16; i++) {
            float m = mymz[2 * i], z = mymz[2 * i + 1];
            float invz = 1.0f / z;
            float4 c4 = *(float4*)(myhc + i * 132 + 4 * lane);
            float cv[4] = {c4.x * invz, c4.y * invz, c4.z * invz, c4.w * invz};
            float4 h4 = *(const float4*)(Hp + i * DD + 4 * lane);   // L2-hot re-read
            float hv[4] = {h4.x, h4.y, h4.z, h4.w};

            float nM = fmaxf(Mw, m);
            float aa = __expf(Mw - nM);
            float ee = __expf(m - nM);
#pragma unroll
            for (int j = 0; j < 4; j++) qacc[j] = qacc[j] * aa + ee * hv[j];
            Zw = Zw * aa + ee;
            Mw = nM;

            int tk = tok_s[it * 128 + wid * 16 + i];
            if (tk != 0) {
                float4 m4 = *(const float4*)(Mp + i * DD + 4 * lane);
                float mv[4] = {m4.x, m4.y, m4.z, m4.w};
#pragma unroll
                for (int j = 0; j < 4; j++) {
                    pm_h[j]  = fmaxf(pm_h[j],  hv[j]);
                    pm_c[j]  = fmaxf(pm_c[j],  cv[j]);
                    pm_hc[j] = fmaxf(pm_hc[j], hv[j] * cv[j]);
                    pm_m[j]  = fmaxf(pm_m[j],  mv[j]);
                    mxh[j]   = fmaxf(mxh[j],   hv[j]);
                    mnh[j]   = fminf(mnh[j],   hv[j]);
                }
            }
        }
        __syncwarp();
    }

    // ---------------- block reduction -> tile partials ----------------
    __syncthreads();
    if (lane == 0) { mzs[wid * 2] = Mw; mzs[wid * 2 + 1] = Zw; }
    __syncthreads();
    float Mb = mzs[0];
#pragma unroll
    for (int w = 1; w < 8; w++) Mb = fmaxf(Mb, mzs[2 * w]);

    float* pout = g_part + ((size_t)b * NT + t) * 1024;
    float sc = __expf(Mw - Mb);

    *(float4*)(red + wid * DD + 4 * lane) =
        make_float4(qacc[0] * sc, qacc[1] * sc, qacc[2] * sc, qacc[3] * sc);
    __syncthreads();
    if (tid < DD) {
        float r = 0.f;
#pragma unroll
        for (int w = 0; w < 8; w++) r += red[w * DD + tid];
        pout[tid] = r;
    }

#define BLK_MAXRED(arr, off)                                                   \
    do {                                                                       \
        __syncthreads();                                                       \
        *(float4*)(red + wid * DD + 4 * lane) =                                \
            make_float4((arr)[0], (arr)[1], (arr)[2], (arr)[3]);               \
        __syncthreads();                                                       \
        if (tid < DD) {                                                        \
            float r = red[tid];                                                \
            for (int w = 1; w < 8; w++) r = fmaxf(r, red[w * DD + tid]);       \
            pout[(off) + tid] = r;                                             \
        }                                                                      \
    } while (0)

    BLK_MAXRED(pm_h, 128);
    BLK_MAXRED(pm_c, 256);
    BLK_MAXRED(pm_hc, 384);
    BLK_MAXRED(pm_m, 512);
    BLK_MAXRED(mxh, 640);

    __syncthreads();
    *(float4*)(red + wid * DD + 4 * lane) = make_float4(mnh[0], mnh[1], mnh[2], mnh[3]);
    __syncthreads();
    if (tid < DD) {
        float r = red[tid];
#pragma unroll
        for (int w = 1; w < 8; w++) r = fminf(r, red[w * DD + tid]);
        pout[768 + tid] = r;
    }
    if (tid == 0) {
        float Zt = 0.f;
#pragma unroll
        for (int w = 0; w < 8; w++) Zt += mzs[2 * w + 1] * __expf(mzs[2 * w] - Mb);
        pout[896] = Mb;
        pout[897] = Zt;
    }

    // ---------------- fused finalize: last block of batch b ----------------
    __syncthreads();
    __threadfence();
    if (tid == 0) s_last = (atomicAdd(&g_cnt[b], 1) == NT - 1) ? 1 : 0;
    __syncthreads();
    if (s_last) {
        __threadfence();
        float o0 = 0.f, o1 = 0.f;
        if (tid < DD) {
            int d = tid;
            const float* base = g_part + (size_t)b * NT * 1024;
            float Mg = NEGBIG;
#pragma unroll
            for (int tt = 0; tt < NT; tt++) Mg = fmaxf(Mg, base[tt * 1024 + 896]);
            float Z = 0.f, qa = 0.f;
            float ph = NEGBIG, pc = NEGBIG, phc = NEGBIG, pmx = NEGBIG, xh = NEGBIG, nh = POSBIG;
#pragma unroll
            for (int tt = 0; tt < NT; tt++) {
                const float* pt = base + tt * 1024;
                float scv = __expf(pt[896] - Mg);
                Z  += pt[897] * scv;
                qa += pt[d] * scv;
                ph  = fmaxf(ph,  pt[128 + d]);
                pc  = fmaxf(pc,  pt[256 + d]);
                phc = fmaxf(phc, pt[384 + d]);
                pmx = fmaxf(pmx, pt[512 + d]);
                xh  = fmaxf(xh,  pt[640 + d]);
                nh  = fminf(nh,  pt[768 + d]);
            }
            float q2c = qa / Z;
            float phq = fmaxf(q2c * xh, q2c * nh);
            o0 = ph * Wcls[2 * d] + pc * Wcls[2 * (128 + d)] + phc * Wcls[2 * (256 + d)]
               + phq * Wcls[2 * (384 + d)] + pmx * Wcls[2 * (512 + d)];
            o1 = ph * Wcls[2 * d + 1] + pc * Wcls[2 * (128 + d) + 1] + phc * Wcls[2 * (256 + d) + 1]
               + phq * Wcls[2 * (384 + d) + 1] + pmx * Wcls[2 * (512 + d) + 1];
        }
        __syncthreads();
        float* r0 = red;
        float* r1 = red + 128;
        if (tid < DD) { r0[tid] = o0; r1[tid] = o1; }
        __syncthreads();
        for (int s = 64; s > 0; s >>= 1) {
            if (tid < s) { r0[tid] += r0[tid + s]; r1[tid] += r1[tid + s]; }
            __syncthreads();
        }
        if (tid == 0) {
            out[b * 2]     = r0[0];
            out[b * 2 + 1] = r1[0];
            g_cnt[b] = 0;   // reset for next graph replay
        }
    }
}

// ---------------------------------------------------------------------------
extern "C" void kernel_launch(void* const* d_in, const int* in_sizes, int n_in,
                              void* d_out, int out_size) {
    const float* H     = (const float*)d_in[0];
    const float* U     = (const float*)d_in[1];
    const float* Mm    = (const float*)d_in[2];
    const int*   tok   = (const int*)d_in[3];    // int32 on the wire
    const float* Wattn = (const float*)d_in[4];
    const float* Wcls  = (const float*)d_in[5];
    float*       out   = (float*)d_out;

    cudaFuncSetAttribute(main_kernel, cudaFuncAttributeMaxDynamicSharedMemorySize, SMEM_BYTES);

    vt_kernel<<<dim3(8, BB), 256>>>(U, Wattn);
    main_kernel<<<dim3(NT, BB), 256, SMEM_BYTES>>>(H, U, Mm, tok, Wcls, out);
}

// round 8
// speedup vs baseline: 1.2908x; 1.0992x over previous
#include <cuda_runtime.h>
#include <cuda_bf16.h>
#include <cstdint>

#define BB 32
#define PP 4096
#define QQ 64
#define DD 128
#define NT 8
#define TILE 512
#define NEGBIG (-1e30f)
#define POSBIG (1e30f)

// ---- main kernel smem layout (32-bit words) ----
#define SM_UHI   0        // U hi packed  [qp*136 + d]   32*136 = 4352
#define SM_ULO   4352     // U lo packed                  4352
#define SM_VTHI  8704     // Vt hi packed [dp*72 + q]    64*72  = 4608
#define SM_VTLO  13312    // Vt lo packed                 4608
#define SM_HC    17920    // per warp c2q half buffer 16*68 = 1088; 8*1088 = 8704
#define SM_MZ    26624    // per warp row (m,z) 16*2      8*32 = 256
#define SM_TOK   26880    // tok ints                     512
#define SM_MZS   27392    // warp M/Z                     16
#define SM_TOTAL 27408
#define SMEM_BYTES (SM_TOTAL * 4)

// device scratch (zero-initialized)
__device__ float g_Vt[BB * DD * QQ];      // Vt[b][d][q]
__device__ float g_part[BB * NT * 1024];  // per (b,tile) partials
__device__ int   g_cnt[BB];               // arrival counters (left 0 after each call)

// ---------------------------------------------------------------------------
__device__ __forceinline__ void mma_bf16(float* d,
    uint32_t a0, uint32_t a1, uint32_t a2, uint32_t a3,
    uint32_t b0, uint32_t b1)
{
    asm volatile(
        "mma.sync.aligned.m16n8k16.row.col.f32.bf16.bf16.f32 "
        "{%0,%1,%2,%3}, {%4,%5,%6,%7}, {%8,%9}, {%0,%1,%2,%3};"
        : "+f"(d[0]), "+f"(d[1]), "+f"(d[2]), "+f"(d[3])
        : "r"(a0), "r"(a1), "r"(a2), "r"(a3), "r"(b0), "r"(b1));
}

// split (x0,x1) into packed bf16x2 hi and lo (x = hi + lo + O(2^-17 x))
__device__ __forceinline__ void packsplit(float x0, float x1, uint32_t& hi, uint32_t& lo) {
    __nv_bfloat162 h = __float22bfloat162_rn(make_float2(x0, x1));
    float2 hf = __bfloat1622float2(h);
    __nv_bfloat162 l = __float22bfloat162_rn(make_float2(x0 - hf.x, x1 - hf.y));
    hi = *reinterpret_cast<uint32_t*>(&h);
    lo = *reinterpret_cast<uint32_t*>(&l);
}

// ---------------------------------------------------------------------------
// Kernel 1: Vt[b][d][q] = sum_e W[d,e]*U[b,q,e] (fp32 exact). grid (8,32).
// ---------------------------------------------------------------------------
__global__ void vt_kernel(const float* __restrict__ U, const float* __restrict__ W) {
    __shared__ float U_s[QQ * 129];
    __shared__ float W_s[16 * DD];
    int b = blockIdx.y, dbase = blockIdx.x * 16, tid = threadIdx.x;

    const float* Ub = U + (size_t)b * QQ * DD;
    for (int i = tid; i < QQ * DD; i += 256)
        U_s[(i >> 7) * 129 + (i & 127)] = Ub[i];
    for (int i = tid; i < 16 * DD; i += 256)
        W_s[i] = W[(size_t)dbase * DD + i];
    __syncthreads();

    int q = tid & 63, dg = tid >> 6;
    float acc[4] = {0.f, 0.f, 0.f, 0.f};
#pragma unroll 4
    for (int e = 0; e < DD; e++) {
        float u = U_s[q * 129 + e];
#pragma unroll
        for (int k = 0; k < 4; k++)
            acc[k] += u * W_s[(dg * 4 + k) * DD + e];
    }
#pragma unroll
    for (int k = 0; k < 4; k++)
        g_Vt[((size_t)b * DD + dbase + dg * 4 + k) * QQ + q] = acc[k];
}

// ---------------------------------------------------------------------------
// Kernel 2: fused attention (bf16-split MMA) + pooling + fused finalize.
// grid (NT, 32), 256 threads, 2 CTAs/SM. Warp owns 16 p-rows per iteration.
// ---------------------------------------------------------------------------
__global__ void __launch_bounds__(256, 2) main_kernel(
    const float* __restrict__ H, const float* __restrict__ U,
    const float* __restrict__ Mm, const int* __restrict__ tok,
    const float* __restrict__ Wcls, float* __restrict__ out)
{
    extern __shared__ float sm[];
    uint32_t* U_hi  = (uint32_t*)(sm + SM_UHI);
    uint32_t* U_lo  = (uint32_t*)(sm + SM_ULO);
    uint32_t* Vt_hi = (uint32_t*)(sm + SM_VTHI);
    uint32_t* Vt_lo = (uint32_t*)(sm + SM_VTLO);
    float*    hc_sb = sm + SM_HC;
    float*    mz_sb = sm + SM_MZ;
    int*      tok_s = (int*)(sm + SM_TOK);
    float*    mzs   = sm + SM_MZS;
    float*    red   = sm + SM_HC;   // alias: HC dead by the time red is used
    __shared__ int s_last;

    int t = blockIdx.x, b = blockIdx.y;
    int pstart = t * TILE;
    int tid = threadIdx.x, wid = tid >> 5, lane = tid & 31;
    int g = lane >> 2, tg = lane & 3;

    // ---- stage packed U (pairs over q), packed Vt (pairs over d), tok ----
    const float* Ub = U + (size_t)b * QQ * DD;
    for (int i = tid; i < 32 * DD; i += 256) {
        int pq = i >> 7, d = i & 127;
        uint32_t hi, lo;
        packsplit(Ub[(2 * pq) * DD + d], Ub[(2 * pq + 1) * DD + d], hi, lo);
        U_hi[pq * 136 + d] = hi; U_lo[pq * 136 + d] = lo;
    }
    const float* Vtb = g_Vt + (size_t)b * DD * QQ;
    for (int i = tid; i < 64 * QQ; i += 256) {
        int pd = i >> 6, q = i & 63;
        uint32_t hi, lo;
        packsplit(Vtb[(2 * pd) * QQ + q], Vtb[(2 * pd + 1) * QQ + q], hi, lo);
        Vt_hi[pd * 72 + q] = hi; Vt_lo[pd * 72 + q] = lo;
    }
    const int* tokb = tok + (size_t)b * PP + pstart;
    for (int i = tid; i < TILE; i += 256) tok_s[i] = tokb[i];
    __syncthreads();

    float* myhc = hc_sb + wid * 1088;   // 16 rows * 68 (half-width c2q bounce)
    float* mymz = mz_sb + wid * 32;

    // per-warp running partials (lane covers d = 4*lane + j)
    float pm_h[4], pm_c[4], pm_hc[4], pm_m[4], mxh[4], mnh[4], qacc[4];
#pragma unroll
    for (int j = 0; j < 4; j++) {
        pm_h[j] = NEGBIG; pm_c[j] = NEGBIG; pm_hc[j] = NEGBIG; pm_m[j] = NEGBIG;
        mxh[j] = NEGBIG;  mnh[j] = POSBIG;  qacc[j] = 0.f;
    }
    float Mw = NEGBIG, Zw = 0.f;

    for (int it = 0; it < 4; it++) {
        int p0 = pstart + it * 128 + wid * 16;
        const float* Hp = H + ((size_t)b * PP + p0) * DD;
        const float* Mp = Mm + ((size_t)b * PP + p0) * DD;

        // ---- S = H . Vt^T (3-term bf16 split); A-frags straight from gmem ----
        float sacc[8][4];
#pragma unroll
        for (int nt = 0; nt < 8; nt++)
            sacc[nt][0] = sacc[nt][1] = sacc[nt][2] = sacc[nt][3] = 0.f;

#pragma unroll
        for (int kt = 0; kt < 8; kt++) {
            float2 f0 = *(const float2*)(Hp + g * DD + 16 * kt + 2 * tg);
            float2 f1 = *(const float2*)(Hp + (g + 8) * DD + 16 * kt + 2 * tg);
            float2 f2 = *(const float2*)(Hp + g * DD + 16 * kt + 8 + 2 * tg);
            float2 f3 = *(const float2*)(Hp + (g + 8) * DD + 16 * kt + 8 + 2 * tg);
            uint32_t ah0, al0, ah1, al1, ah2, al2, ah3, al3;
            packsplit(f0.x, f0.y, ah0, al0);
            packsplit(f1.x, f1.y, ah1, al1);
            packsplit(f2.x, f2.y, ah2, al2);
            packsplit(f3.x, f3.y, ah3, al3);
#pragma unroll
            for (int nt = 0; nt < 8; nt++) {
                int c = 8 * nt + g;
                uint32_t bh0 = Vt_hi[(8 * kt + tg) * 72 + c];
                uint32_t bh1 = Vt_hi[(8 * kt + tg + 4) * 72 + c];
                uint32_t bl0 = Vt_lo[(8 * kt + tg) * 72 + c];
                uint32_t bl1 = Vt_lo[(8 * kt + tg + 4) * 72 + c];
                mma_bf16(sacc[nt], ah0, ah1, ah2, ah3, bh0, bh1);
                mma_bf16(sacc[nt], ah0, ah1, ah2, ah3, bl0, bl1);
                mma_bf16(sacc[nt], al0, al1, al2, al3, bh0, bh1);
            }
        }

        // ---- softmax over q: rows g and g+8 ----
        float m0 = NEGBIG, m1 = NEGBIG;
#pragma unroll
        for (int nt = 0; nt < 8; nt++) {
            m0 = fmaxf(m0, fmaxf(sacc[nt][0], sacc[nt][1]));
            m1 = fmaxf(m1, fmaxf(sacc[nt][2], sacc[nt][3]));
        }
        m0 = fmaxf(m0, __shfl_xor_sync(0xffffffffu, m0, 1));
        m0 = fmaxf(m0, __shfl_xor_sync(0xffffffffu, m0, 2));
        m1 = fmaxf(m1, __shfl_xor_sync(0xffffffffu, m1, 1));
        m1 = fmaxf(m1, __shfl_xor_sync(0xffffffffu, m1, 2));

        float z0 = 0.f, z1 = 0.f;
#pragma unroll
        for (int nt = 0; nt < 8; nt++) {
            sacc[nt][0] = __expf(sacc[nt][0] - m0);
            sacc[nt][1] = __expf(sacc[nt][1] - m0);
            sacc[nt][2] = __expf(sacc[nt][2] - m1);
            sacc[nt][3] = __expf(sacc[nt][3] - m1);
            z0 += sacc[nt][0] + sacc[nt][1];
            z1 += sacc[nt][2] + sacc[nt][3];
        }
        z0 += __shfl_xor_sync(0xffffffffu, z0, 1);
        z0 += __shfl_xor_sync(0xffffffffu, z0, 2);
        z1 += __shfl_xor_sync(0xffffffffu, z1, 1);
        z1 += __shfl_xor_sync(0xffffffffu, z1, 2);

        if (tg == 0) {
            mymz[2 * g] = m0;           mymz[2 * g + 1] = z0;
            mymz[2 * (g + 8)] = m1;     mymz[2 * (g + 8) + 1] = z1;
        }

        // ---- pack e directly into c2q A-fragments (S C-frag == c2q A-frag) ----
        uint32_t ea_hi[4][4], ea_lo[4][4];
#pragma unroll
        for (int kt = 0; kt < 4; kt++) {
            packsplit(sacc[2 * kt][0],     sacc[2 * kt][1],     ea_hi[kt][0], ea_lo[kt][0]);
            packsplit(sacc[2 * kt][2],     sacc[2 * kt][3],     ea_hi[kt][1], ea_lo[kt][1]);
            packsplit(sacc[2 * kt + 1][0], sacc[2 * kt + 1][1], ea_hi[kt][2], ea_lo[kt][2]);
            packsplit(sacc[2 * kt + 1][2], sacc[2 * kt + 1][3], ea_hi[kt][3], ea_lo[kt][3]);
        }
        __syncwarp();   // mymz visible to all lanes

        // ---- c2q in two d-column halves; pooling per half ----
#pragma unroll
        for (int half = 0; half < 2; half++) {
            float cacc[8][4];
#pragma unroll
            for (int ntl = 0; ntl < 8; ntl++)
                cacc[ntl][0] = cacc[ntl][1] = cacc[ntl][2] = cacc[ntl][3] = 0.f;

#pragma unroll
            for (int kt = 0; kt < 4; kt++) {
#pragma unroll
                for (int ntl = 0; ntl < 8; ntl++) {
                    int c = 64 * half + 8 * ntl + g;
                    int r0i = (8 * kt + tg) * 136 + c;
                    int r1i = (8 * kt + tg + 4) * 136 + c;
                    uint32_t bh0 = U_hi[r0i], bh1 = U_hi[r1i];
                    uint32_t bl0 = U_lo[r0i], bl1 = U_lo[r1i];
                    mma_bf16(cacc[ntl], ea_hi[kt][0], ea_hi[kt][1], ea_hi[kt][2], ea_hi[kt][3], bh0, bh1);
                    mma_bf16(cacc[ntl], ea_hi[kt][0], ea_hi[kt][1], ea_hi[kt][2], ea_hi[kt][3], bl0, bl1);
                    mma_bf16(cacc[ntl], ea_lo[kt][0], ea_lo[kt][1], ea_lo[kt][2], ea_lo[kt][3], bh0, bh1);
                }
            }
            __syncwarp();   // previous half's pooling reads done
#pragma unroll
            for (int ntl = 0; ntl < 8; ntl++) {
                *(float2*)(myhc + g * 68 + 8 * ntl + 2 * tg)       = make_float2(cacc[ntl][0], cacc[ntl][1]);
                *(float2*)(myhc + (g + 8) * 68 + 8 * ntl + 2 * tg) = make_float2(cacc[ntl][2], cacc[ntl][3]);
            }
            __syncwarp();

            if ((lane >> 4) == half) {      // this lane's d-quad (4*lane..+3) is in this half
                int cl = 4 * (lane & 15);
#pragma unroll 2
                for (int i = 0; i < 16; i++) {
                    float m = mymz[2 * i], z = mymz[2 * i + 1];
                    float invz = 1.0f / z;
                    float4 c4 = *(float4*)(myhc + i * 68 + cl);
                    float cv[4] = {c4.x * invz, c4.y * invz, c4.z * invz, c4.w * invz};
                    float4 h4 = *(const float4*)(Hp + i * DD + 4 * lane);
                    float hv[4] = {h4.x, h4.y, h4.z, h4.w};

                    float nM = fmaxf(Mw, m);
                    float aa = __expf(Mw - nM);
                    float ee = __expf(m - nM);
#pragma unroll
                    for (int j = 0; j < 4; j++) qacc[j] = qacc[j] * aa + ee * hv[j];
                    Zw = Zw * aa + ee;
                    Mw = nM;

                    int tk = tok_s[it * 128 + wid * 16 + i];
                    if (tk != 0) {
                        float4 m4 = *(const float4*)(Mp + i * DD + 4 * lane);
                        float mv[4] = {m4.x, m4.y, m4.z, m4.w};
#pragma unroll
                        for (int j = 0; j < 4; j++) {
                            pm_h[j]  = fmaxf(pm_h[j],  hv[j]);
                            pm_c[j]  = fmaxf(pm_c[j],  cv[j]);
                            pm_hc[j] = fmaxf(pm_hc[j], hv[j] * cv[j]);
                            pm_m[j]  = fmaxf(pm_m[j],  mv[j]);
                            mxh[j]   = fmaxf(mxh[j],   hv[j]);
                            mnh[j]   = fminf(mnh[j],   hv[j]);
                        }
                    }
                }
            }
            __syncwarp();
        }
    }

    // ---------------- block reduction -> tile partials ----------------
    __syncthreads();
    if (lane == 0) { mzs[wid * 2] = Mw; mzs[wid * 2 + 1] = Zw; }
    __syncthreads();
    float Mb = mzs[0];
#pragma unroll
    for (int w = 1; w < 8; w++) Mb = fmaxf(Mb, mzs[2 * w]);

    float* pout = g_part + ((size_t)b * NT + t) * 1024;
    float sc = __expf(Mw - Mb);

    *(float4*)(red + wid * DD + 4 * lane) =
        make_float4(qacc[0] * sc, qacc[1] * sc, qacc[2] * sc, qacc[3] * sc);
    __syncthreads();
    if (tid < DD) {
        float r = 0.f;
#pragma unroll
        for (int w = 0; w < 8; w++) r += red[w * DD + tid];
        pout[tid] = r;
    }

#define BLK_MAXRED(arr, off)                                                   \
    do {                                                                       \
        __syncthreads();                                                       \
        *(float4*)(red + wid * DD + 4 * lane) =                                \
            make_float4((arr)[0], (arr)[1], (arr)[2], (arr)[3]);               \
        __syncthreads();                                                       \
        if (tid < DD) {                                                        \
            float r = red[tid];                                                \
            for (int w = 1; w < 8; w++) r = fmaxf(r, red[w * DD + tid]);       \
            pout[(off) + tid] = r;                                             \
        }                                                                      \
    } while (0)

    BLK_MAXRED(pm_h, 128);
    BLK_MAXRED(pm_c, 256);
    BLK_MAXRED(pm_hc, 384);
    BLK_MAXRED(pm_m, 512);
    BLK_MAXRED(mxh, 640);

    __syncthreads();
    *(float4*)(red + wid * DD + 4 * lane) = make_float4(mnh[0], mnh[1], mnh[2], mnh[3]);
    __syncthreads();
    if (tid < DD) {
        float r = red[tid];
#pragma unroll
        for (int w = 1; w < 8; w++) r = fminf(r, red[w * DD + tid]);
        pout[768 + tid] = r;
    }
    if (tid == 0) {
        float Zt = 0.f;
#pragma unroll
        for (int w = 0; w < 8; w++) Zt += mzs[2 * w + 1] * __expf(mzs[2 * w] - Mb);
        pout[896] = Mb;
        pout[897] = Zt;
    }

    // ---------------- fused finalize: last block of batch b ----------------
    __syncthreads();
    __threadfence();
    if (tid == 0) s_last = (atomicAdd(&g_cnt[b], 1) == NT - 1) ? 1 : 0;
    __syncthreads();
    if (s_last) {
        __threadfence();
        float o0 = 0.f, o1 = 0.f;
        if (tid < DD) {
            int d = tid;
            const float* base = g_part + (size_t)b * NT * 1024;
            float Mg = NEGBIG;
#pragma unroll
            for (int tt = 0; tt < NT; tt++) Mg = fmaxf(Mg, base[tt * 1024 + 896]);
            float Z = 0.f, qa = 0.f;
            float ph = NEGBIG, pc = NEGBIG, phc = NEGBIG, pmx = NEGBIG, xh = NEGBIG, nh = POSBIG;
#pragma unroll
            for (int tt = 0; tt < NT; tt++) {
                const float* pt = base + tt * 1024;
                float scv = __expf(pt[896] - Mg);
                Z  += pt[897] * scv;
                qa += pt[d] * scv;
                ph  = fmaxf(ph,  pt[128 + d]);
                pc  = fmaxf(pc,  pt[256 + d]);
                phc = fmaxf(phc, pt[384 + d]);
                pmx = fmaxf(pmx, pt[512 + d]);
                xh  = fmaxf(xh,  pt[640 + d]);
                nh  = fminf(nh,  pt[768 + d]);
            }
            float q2c = qa / Z;
            float phq = fmaxf(q2c * xh, q2c * nh);
            o0 = ph * Wcls[2 * d] + pc * Wcls[2 * (128 + d)] + phc * Wcls[2 * (256 + d)]
               + phq * Wcls[2 * (384 + d)] + pmx * Wcls[2 * (512 + d)];
            o1 = ph * Wcls[2 * d + 1] + pc * Wcls[2 * (128 + d) + 1] + phc * Wcls[2 * (256 + d) + 1]
               + phq * Wcls[2 * (384 + d) + 1] + pmx * Wcls[2 * (512 + d) + 1];
        }
        __syncthreads();
        float* r0 = red;
        float* r1 = red + 128;
        if (tid < DD) { r0[tid] = o0; r1[tid] = o1; }
        __syncthreads();
        for (int s = 64; s > 0; s >>= 1) {
            if (tid < s) { r0[tid] += r0[tid + s]; r1[tid] += r1[tid + s]; }
            __syncthreads();
        }
        if (tid == 0) {
            out[b * 2]     = r0[0];
            out[b * 2 + 1] = r1[0];
            g_cnt[b] = 0;   // reset for next graph replay
        }
    }
}

// ---------------------------------------------------------------------------
extern "C" void kernel_launch(void* const* d_in, const int* in_sizes, int n_in,
                              void* d_out, int out_size) {
    const float* H     = (const float*)d_in[0];
    const float* U     = (const float*)d_in[1];
    const float* Mm    = (const float*)d_in[2];
    const int*   tok   = (const int*)d_in[3];    // int32 on the wire
    const float* Wattn = (const float*)d_in[4];
    const float* Wcls  = (const float*)d_in[5];
    float*       out   = (float*)d_out;

    cudaFuncSetAttribute(main_kernel, cudaFuncAttributeMaxDynamicSharedMemorySize, SMEM_BYTES);

    vt_kernel<<<dim3(8, BB), 256>>>(U, Wattn);
    main_kernel<<<dim3(NT, BB), 256, SMEM_BYTES>>>(H, U, Mm, tok, Wcls, out);
}